// round 5
// baseline (speedup 1.0000x reference)
#include <cuda_runtime.h>
#include <cstdint>

#define N_NODES 100000
#define N_PAIRS 640000
#define F_TOTAL 128
#define N_HEADS 8
#define HEAD_DIM 16

// projected q in (node, 128) layout.
// kv: per node 256 floats as 32 lane-chunks of {k quad (4), v quad (4)} so one
// 32-byte load per lane fetches both k and v for that lane's 4 features.
__device__ float g_q [N_NODES * F_TOTAL];
__device__ __align__(32) float g_kv[N_NODES * F_TOTAL * 2];

// CSR-by-idx_i machinery (rebuilt every launch; deterministic work)
__device__ int  g_cnt[N_NODES];      // zeroed by aggregate_kernel at end of each call
__device__ int  g_cursor[N_NODES];   // scan1 writes local prefix; scatter bumps it
__device__ int4 g_meta[N_PAIRS];     // {pair_id, idx_j, phi_bits, 0} grouped by idx_i
#define NB1 98                        // ceil(100000/1024)
__device__ int g_bsum[NB1];

#define W_STRIDE 260

// 256-bit gather with L2 evict-last (pins the 102MB kv array in L2 against the
// streaming w traffic). v8 is the only width ptxas allows this hint on.
__device__ __forceinline__ void ldg_kv(const float* p, float4& k, float4& v)
{
    uint32_t a0, a1, a2, a3, a4, a5, a6, a7;
    asm volatile("ld.global.nc.L2::evict_last.v8.b32 {%0,%1,%2,%3,%4,%5,%6,%7}, [%8];"
                 : "=r"(a0), "=r"(a1), "=r"(a2), "=r"(a3),
                   "=r"(a4), "=r"(a5), "=r"(a6), "=r"(a7)
                 : "l"(p));
    k = make_float4(__uint_as_float(a0), __uint_as_float(a1),
                    __uint_as_float(a2), __uint_as_float(a3));
    v = make_float4(__uint_as_float(a4), __uint_as_float(a5),
                    __uint_as_float(a6), __uint_as_float(a7));
}

__global__ void __launch_bounds__(256) proj_kernel(
    const float* __restrict__ x,
    const float* __restrict__ wq,
    const float* __restrict__ wk,
    const float* __restrict__ wv)
{
    __shared__ float sq[N_HEADS * W_STRIDE];
    __shared__ float sk[N_HEADS * W_STRIDE];
    __shared__ float sv[N_HEADS * W_STRIDE];

    for (int i = threadIdx.x; i < N_HEADS * HEAD_DIM * HEAD_DIM; i += 256) {
        int h = i >> 8;
        int r = i & 255;
        sq[h * W_STRIDE + r] = wq[i];
        sk[h * W_STRIDE + r] = wk[i];
        sv[h * W_STRIDE + r] = wv[i];
    }
    __syncthreads();

    int gid = blockIdx.x * 256 + threadIdx.x;   // node*8 + head
    if (gid >= N_NODES * N_HEADS) return;
    int n = gid >> 3;
    int h = gid & 7;

    const float4* xp = reinterpret_cast<const float4*>(x + (size_t)n * F_TOTAL + h * HEAD_DIM);
    float4 xv0 = xp[0], xv1 = xp[1], xv2 = xp[2], xv3 = xp[3];
    float xr[16] = {xv0.x, xv0.y, xv0.z, xv0.w,
                    xv1.x, xv1.y, xv1.z, xv1.w,
                    xv2.x, xv2.y, xv2.z, xv2.w,
                    xv3.x, xv3.y, xv3.z, xv3.w};

    const float4* wq4 = reinterpret_cast<const float4*>(sq + h * W_STRIDE);
    const float4* wk4 = reinterpret_cast<const float4*>(sk + h * W_STRIDE);
    const float4* wv4 = reinterpret_cast<const float4*>(sv + h * W_STRIDE);

    float qo[16], ko[16], vo[16];
#pragma unroll
    for (int e = 0; e < 16; e++) {
        float aq = 0.f, ak = 0.f, av = 0.f;
#pragma unroll
        for (int d4 = 0; d4 < 4; d4++) {
            float4 a = wq4[e * 4 + d4];
            float4 b = wk4[e * 4 + d4];
            float4 c = wv4[e * 4 + d4];
            float x0 = xr[4 * d4 + 0], x1 = xr[4 * d4 + 1];
            float x2 = xr[4 * d4 + 2], x3 = xr[4 * d4 + 3];
            aq += x0 * a.x + x1 * a.y + x2 * a.z + x3 * a.w;
            ak += x0 * b.x + x1 * b.y + x2 * b.z + x3 * b.w;
            av += x0 * c.x + x1 * c.y + x2 * c.z + x3 * c.w;
        }
        qo[e] = aq; ko[e] = ak; vo[e] = av;
    }

    float4* qdst = reinterpret_cast<float4*>(g_q + (size_t)n * F_TOTAL + h * HEAD_DIM);
    // kv interleaved: lane (h*4+t) chunk at n*256 + lane*8 floats: k quad then v quad
    float4* kvdst = reinterpret_cast<float4*>(g_kv + (size_t)n * (F_TOTAL * 2));
#pragma unroll
    for (int t = 0; t < 4; t++) {
        qdst[t] = make_float4(qo[4*t], qo[4*t+1], qo[4*t+2], qo[4*t+3]);
        int lane = h * 4 + t;
        kvdst[lane * 2 + 0] = make_float4(ko[4*t], ko[4*t+1], ko[4*t+2], ko[4*t+3]);
        kvdst[lane * 2 + 1] = make_float4(vo[4*t], vo[4*t+1], vo[4*t+2], vo[4*t+3]);
    }
}

__global__ void __launch_bounds__(256) hist_kernel(const int* __restrict__ idx_i)
{
    int p = blockIdx.x * 256 + threadIdx.x;
    if (p < N_PAIRS) atomicAdd(&g_cnt[idx_i[p]], 1);
}

// per-block (1024-element) exclusive scan of g_cnt into g_cursor; block totals to g_bsum
__global__ void __launch_bounds__(256) scan1_kernel()
{
    __shared__ int sh[256];
    int t = threadIdx.x;
    int base = blockIdx.x * 1024 + t * 4;
    int v0 = (base + 0 < N_NODES) ? g_cnt[base + 0] : 0;
    int v1 = (base + 1 < N_NODES) ? g_cnt[base + 1] : 0;
    int v2 = (base + 2 < N_NODES) ? g_cnt[base + 2] : 0;
    int v3 = (base + 3 < N_NODES) ? g_cnt[base + 3] : 0;
    int s = v0 + v1 + v2 + v3;
    sh[t] = s;
    __syncthreads();
    for (int off = 1; off < 256; off <<= 1) {
        int add = (t >= off) ? sh[t - off] : 0;
        __syncthreads();
        sh[t] += add;
        __syncthreads();
    }
    int excl = sh[t] - s;
    if (base + 0 < N_NODES) g_cursor[base + 0] = excl;
    if (base + 1 < N_NODES) g_cursor[base + 1] = excl + v0;
    if (base + 2 < N_NODES) g_cursor[base + 2] = excl + v0 + v1;
    if (base + 3 < N_NODES) g_cursor[base + 3] = excl + v0 + v1 + v2;
    if (t == 255) g_bsum[blockIdx.x] = sh[255];
}

// exclusive scan of the NB1 block sums (single block)
__global__ void __launch_bounds__(128) scan2_kernel()
{
    __shared__ int sh[128];
    int t = threadIdx.x;
    int v = (t < NB1) ? g_bsum[t] : 0;
    sh[t] = v;
    __syncthreads();
    for (int off = 1; off < 128; off <<= 1) {
        int add = (t >= off) ? sh[t - off] : 0;
        __syncthreads();
        sh[t] += add;
        __syncthreads();
    }
    if (t < NB1) g_bsum[t] = sh[t] - v;
}

// scatter full metadata record; global slot = local cursor bump + chunk offset
__global__ void __launch_bounds__(256) scatter_kernel(
    const int* __restrict__ idx_i,
    const int* __restrict__ idx_j,
    const float* __restrict__ phi)
{
    int p = blockIdx.x * 256 + threadIdx.x;
    if (p < N_PAIRS) {
        int i = idx_i[p];
        int pos = atomicAdd(&g_cursor[i], 1) + g_bsum[i >> 10];
        g_meta[pos] = make_int4(p, idx_j[p], __float_as_int(phi[p]), 0);
    }
}

// One warp per node, depth-2 pipeline, one 256-bit kv gather per lane per edge.
__global__ void __launch_bounds__(256) aggregate_kernel(
    const float* __restrict__ w_ij,
    float*       __restrict__ out)
{
    int node = blockIdx.x * 8 + (threadIdx.x >> 5);
    if (node >= N_NODES) return;
    int lane = threadIdx.x & 31;

    int cnt = g_cnt[node];
    // cursor now = local_excl + cnt; global start = cursor + bsum - cnt
    int start = g_cursor[node] + g_bsum[node >> 10] - cnt;

    const float4* w4 = reinterpret_cast<const float4*>(w_ij);

    float4 q = reinterpret_cast<const float4*>(g_q)[(size_t)node * 32 + lane];
    float4 acc = make_float4(0.f, 0.f, 0.f, 0.f);

    float4 wA, kA, vA, wB, kB, vB;
    float phA = 0.f, phB = 0.f;

    if (cnt > 0) {
        int4 m = __ldcs(&g_meta[start]);
        phA = __int_as_float(m.z);
        wA = __ldcs(w4 + (size_t)m.x * 32 + lane);                       // stream
        ldg_kv(g_kv + (size_t)m.y * (F_TOTAL * 2) + lane * 8, kA, vA);   // pinned
    }
    if (cnt > 1) {
        int4 m = __ldcs(&g_meta[start + 1]);
        phB = __int_as_float(m.z);
        wB = __ldcs(w4 + (size_t)m.x * 32 + lane);
        ldg_kv(g_kv + (size_t)m.y * (F_TOTAL * 2) + lane * 8, kB, vB);
    }

    for (int e = 0; e < cnt; e++) {
        float4 wc = wA, kc = kA, vc = vA; float phc = phA;
        wA = wB; kA = kB; vA = vB; phA = phB;
        if (e + 2 < cnt) {
            int4 m = __ldcs(&g_meta[start + e + 2]);
            phB = __int_as_float(m.z);
            wB = __ldcs(w4 + (size_t)m.x * 32 + lane);
            ldg_kv(g_kv + (size_t)m.y * (F_TOTAL * 2) + lane * 8, kB, vB);
        }
        float part = q.x * wc.x * kc.x + q.y * wc.y * kc.y
                   + q.z * wc.z * kc.z + q.w * wc.w * kc.w;
        part += __shfl_xor_sync(0xFFFFFFFFu, part, 1);
        part += __shfl_xor_sync(0xFFFFFFFFu, part, 2);

        float alpha = part * 0.25f * phc;   // 1/sqrt(16)
        acc.x += alpha * vc.x;
        acc.y += alpha * vc.y;
        acc.z += alpha * vc.z;
        acc.w += alpha * vc.w;
    }
    reinterpret_cast<float4*>(out)[(size_t)node * 32 + lane] = acc;

    // reset degree array for the next (identical) invocation
    if (lane == 0) g_cnt[node] = 0;
}

extern "C" void kernel_launch(void* const* d_in, const int* in_sizes, int n_in,
                              void* d_out, int out_size)
{
    const float* x      = (const float*)d_in[0];
    const float* w_ij   = (const float*)d_in[1];
    const int*   idx_i  = (const int*)  d_in[2];
    const int*   idx_j  = (const int*)  d_in[3];
    const float* phi    = (const float*)d_in[4];
    const float* wq     = (const float*)d_in[5];
    const float* wk     = (const float*)d_in[6];
    const float* wv     = (const float*)d_in[7];
    float* out = (float*)d_out;

    proj_kernel<<<(N_NODES * N_HEADS + 255) / 256, 256>>>(x, wq, wk, wv);
    hist_kernel<<<(N_PAIRS + 255) / 256, 256>>>(idx_i);
    scan1_kernel<<<NB1, 256>>>();
    scan2_kernel<<<1, 128>>>();
    scatter_kernel<<<(N_PAIRS + 255) / 256, 256>>>(idx_i, idx_j, phi);
    aggregate_kernel<<<(N_NODES + 7) / 8, 256>>>(w_ij, out);
}

// round 6
// speedup vs baseline: 1.2642x; 1.2642x over previous
#include <cuda_runtime.h>
#include <cuda_fp16.h>
#include <cstdint>

#define N_NODES 100000
#define N_PAIRS 640000
#define F_TOTAL 128
#define N_HEADS 8
#define HEAD_DIM 16

// projected q in (node, 128) fp32 layout.
// kv in fp16, interleaved per lane: node n, lane l -> uint4 = {k quad, v quad}
// for features [4l, 4l+4). One 16B load per lane fetches both.
__device__ float g_q[N_NODES * F_TOTAL];
__device__ uint4 g_kv[N_NODES * 32];

// CSR-by-idx_i machinery (round-4 proven structure)
__device__ int  g_cnt[N_NODES];
__device__ int  g_rowptr[N_NODES];
__device__ int  g_cursor[N_NODES];
__device__ int4 g_meta[N_PAIRS];     // {pair_id, idx_j, phi_bits, 0} grouped by idx_i
#define NB1 98                        // ceil(100000/1024)
__device__ int g_bsum[NB1];

#define W_STRIDE 260

__global__ void __launch_bounds__(256) proj_kernel(
    const float* __restrict__ x,
    const float* __restrict__ wq,
    const float* __restrict__ wk,
    const float* __restrict__ wv)
{
    __shared__ float sq[N_HEADS * W_STRIDE];
    __shared__ float sk[N_HEADS * W_STRIDE];
    __shared__ float sv[N_HEADS * W_STRIDE];

    for (int i = threadIdx.x; i < N_HEADS * HEAD_DIM * HEAD_DIM; i += 256) {
        int h = i >> 8;
        int r = i & 255;
        sq[h * W_STRIDE + r] = wq[i];
        sk[h * W_STRIDE + r] = wk[i];
        sv[h * W_STRIDE + r] = wv[i];
    }
    __syncthreads();

    int gid = blockIdx.x * 256 + threadIdx.x;   // node*8 + head
    if (gid >= N_NODES * N_HEADS) return;
    int n = gid >> 3;
    int h = gid & 7;

    const float4* xp = reinterpret_cast<const float4*>(x + (size_t)n * F_TOTAL + h * HEAD_DIM);
    float4 xv0 = xp[0], xv1 = xp[1], xv2 = xp[2], xv3 = xp[3];
    float xr[16] = {xv0.x, xv0.y, xv0.z, xv0.w,
                    xv1.x, xv1.y, xv1.z, xv1.w,
                    xv2.x, xv2.y, xv2.z, xv2.w,
                    xv3.x, xv3.y, xv3.z, xv3.w};

    const float4* wq4 = reinterpret_cast<const float4*>(sq + h * W_STRIDE);
    const float4* wk4 = reinterpret_cast<const float4*>(sk + h * W_STRIDE);
    const float4* wv4 = reinterpret_cast<const float4*>(sv + h * W_STRIDE);

    float qo[16], ko[16], vo[16];
#pragma unroll
    for (int e = 0; e < 16; e++) {
        float aq = 0.f, ak = 0.f, av = 0.f;
#pragma unroll
        for (int d4 = 0; d4 < 4; d4++) {
            float4 a = wq4[e * 4 + d4];
            float4 b = wk4[e * 4 + d4];
            float4 c = wv4[e * 4 + d4];
            float x0 = xr[4 * d4 + 0], x1 = xr[4 * d4 + 1];
            float x2 = xr[4 * d4 + 2], x3 = xr[4 * d4 + 3];
            aq += x0 * a.x + x1 * a.y + x2 * a.z + x3 * a.w;
            ak += x0 * b.x + x1 * b.y + x2 * b.z + x3 * b.w;
            av += x0 * c.x + x1 * c.y + x2 * c.z + x3 * c.w;
        }
        qo[e] = aq; ko[e] = ak; vo[e] = av;
    }

    float4* qdst = reinterpret_cast<float4*>(g_q + (size_t)n * F_TOTAL + h * HEAD_DIM);
#pragma unroll
    for (int t = 0; t < 4; t++) {
        qdst[t] = make_float4(qo[4*t], qo[4*t+1], qo[4*t+2], qo[4*t+3]);
        int lane = h * 4 + t;
        half2 k01 = __floats2half2_rn(ko[4*t + 0], ko[4*t + 1]);
        half2 k23 = __floats2half2_rn(ko[4*t + 2], ko[4*t + 3]);
        half2 v01 = __floats2half2_rn(vo[4*t + 0], vo[4*t + 1]);
        half2 v23 = __floats2half2_rn(vo[4*t + 2], vo[4*t + 3]);
        uint4 kvp;
        kvp.x = *reinterpret_cast<uint32_t*>(&k01);
        kvp.y = *reinterpret_cast<uint32_t*>(&k23);
        kvp.z = *reinterpret_cast<uint32_t*>(&v01);
        kvp.w = *reinterpret_cast<uint32_t*>(&v23);
        g_kv[(size_t)n * 32 + lane] = kvp;
    }
}

__global__ void __launch_bounds__(256) zero_cnt_kernel()
{
    int i = blockIdx.x * 256 + threadIdx.x;
    if (i < N_NODES) g_cnt[i] = 0;
}

__global__ void __launch_bounds__(256) hist_kernel(const int* __restrict__ idx_i)
{
    int p = blockIdx.x * 256 + threadIdx.x;
    if (p < N_PAIRS) atomicAdd(&g_cnt[idx_i[p]], 1);
}

__global__ void __launch_bounds__(256) scan1_kernel()
{
    __shared__ int sh[256];
    int t = threadIdx.x;
    int base = blockIdx.x * 1024 + t * 4;
    int v0 = (base + 0 < N_NODES) ? g_cnt[base + 0] : 0;
    int v1 = (base + 1 < N_NODES) ? g_cnt[base + 1] : 0;
    int v2 = (base + 2 < N_NODES) ? g_cnt[base + 2] : 0;
    int v3 = (base + 3 < N_NODES) ? g_cnt[base + 3] : 0;
    int s = v0 + v1 + v2 + v3;
    sh[t] = s;
    __syncthreads();
    for (int off = 1; off < 256; off <<= 1) {
        int add = (t >= off) ? sh[t - off] : 0;
        __syncthreads();
        sh[t] += add;
        __syncthreads();
    }
    int excl = sh[t] - s;
    if (base + 0 < N_NODES) g_rowptr[base + 0] = excl;
    if (base + 1 < N_NODES) g_rowptr[base + 1] = excl + v0;
    if (base + 2 < N_NODES) g_rowptr[base + 2] = excl + v0 + v1;
    if (base + 3 < N_NODES) g_rowptr[base + 3] = excl + v0 + v1 + v2;
    if (t == 255) g_bsum[blockIdx.x] = sh[255];
}

__global__ void __launch_bounds__(128) scan2_kernel()
{
    __shared__ int sh[128];
    int t = threadIdx.x;
    int v = (t < NB1) ? g_bsum[t] : 0;
    sh[t] = v;
    __syncthreads();
    for (int off = 1; off < 128; off <<= 1) {
        int add = (t >= off) ? sh[t - off] : 0;
        __syncthreads();
        sh[t] += add;
        __syncthreads();
    }
    if (t < NB1) g_bsum[t] = sh[t] - v;
}

__global__ void __launch_bounds__(256) scan3_kernel()
{
    int i = blockIdx.x * 256 + threadIdx.x;
    if (i < N_NODES) {
        int v = g_rowptr[i] + g_bsum[i >> 10];
        g_rowptr[i] = v;
        g_cursor[i] = v;
    }
}

__global__ void __launch_bounds__(256) scatter_kernel(
    const int* __restrict__ idx_i,
    const int* __restrict__ idx_j,
    const float* __restrict__ phi)
{
    int p = blockIdx.x * 256 + threadIdx.x;
    if (p < N_PAIRS) {
        int i = idx_i[p];
        int pos = atomicAdd(&g_cursor[i], 1);
        g_meta[pos] = make_int4(p, idx_j[p], __float_as_int(phi[p]), 0);
    }
}

// One warp per node, depth-2 pipeline, one 16B kv load per lane per edge.
__global__ void __launch_bounds__(256) aggregate_kernel(
    const float* __restrict__ w_ij,
    float*       __restrict__ out)
{
    int node = blockIdx.x * 8 + (threadIdx.x >> 5);
    if (node >= N_NODES) return;
    int lane = threadIdx.x & 31;

    int start = g_rowptr[node];
    int deg   = g_cnt[node];

    const float4* w4 = reinterpret_cast<const float4*>(w_ij);

    float4 q = reinterpret_cast<const float4*>(g_q)[(size_t)node * 32 + lane];
    float4 acc = make_float4(0.f, 0.f, 0.f, 0.f);

    float4 wA, wB;
    uint4  kvA, kvB;
    float  phA = 0.f, phB = 0.f;

    if (deg > 0) {
        int4 m = g_meta[start];
        phA = __int_as_float(m.z);
        wA  = __ldcs(w4 + (size_t)m.x * 32 + lane);       // one-touch stream
        kvA = __ldg(&g_kv[(size_t)m.y * 32 + lane]);      // resident gather
    }
    if (deg > 1) {
        int4 m = g_meta[start + 1];
        phB = __int_as_float(m.z);
        wB  = __ldcs(w4 + (size_t)m.x * 32 + lane);
        kvB = __ldg(&g_kv[(size_t)m.y * 32 + lane]);
    }

    for (int e = 0; e < deg; e++) {
        float4 wc = wA; uint4 kvc = kvA; float phc = phA;
        wA = wB; kvA = kvB; phA = phB;
        if (e + 2 < deg) {
            int4 m = g_meta[start + e + 2];
            phB = __int_as_float(m.z);
            wB  = __ldcs(w4 + (size_t)m.x * 32 + lane);
            kvB = __ldg(&g_kv[(size_t)m.y * 32 + lane]);
        }
        float2 k01 = __half22float2(*reinterpret_cast<half2*>(&kvc.x));
        float2 k23 = __half22float2(*reinterpret_cast<half2*>(&kvc.y));
        float2 v01 = __half22float2(*reinterpret_cast<half2*>(&kvc.z));
        float2 v23 = __half22float2(*reinterpret_cast<half2*>(&kvc.w));

        float part = q.x * wc.x * k01.x + q.y * wc.y * k01.y
                   + q.z * wc.z * k23.x + q.w * wc.w * k23.y;
        part += __shfl_xor_sync(0xFFFFFFFFu, part, 1);
        part += __shfl_xor_sync(0xFFFFFFFFu, part, 2);

        float alpha = part * 0.25f * phc;   // 1/sqrt(16)
        acc.x += alpha * v01.x;
        acc.y += alpha * v01.y;
        acc.z += alpha * v23.x;
        acc.w += alpha * v23.y;
    }
    reinterpret_cast<float4*>(out)[(size_t)node * 32 + lane] = acc;
}

extern "C" void kernel_launch(void* const* d_in, const int* in_sizes, int n_in,
                              void* d_out, int out_size)
{
    const float* x      = (const float*)d_in[0];
    const float* w_ij   = (const float*)d_in[1];
    const int*   idx_i  = (const int*)  d_in[2];
    const int*   idx_j  = (const int*)  d_in[3];
    const float* phi    = (const float*)d_in[4];
    const float* wq     = (const float*)d_in[5];
    const float* wk     = (const float*)d_in[6];
    const float* wv     = (const float*)d_in[7];
    float* out = (float*)d_out;

    proj_kernel<<<(N_NODES * N_HEADS + 255) / 256, 256>>>(x, wq, wk, wv);

    zero_cnt_kernel<<<(N_NODES + 255) / 256, 256>>>();
    hist_kernel<<<(N_PAIRS + 255) / 256, 256>>>(idx_i);
    scan1_kernel<<<NB1, 256>>>();
    scan2_kernel<<<1, 128>>>();
    scan3_kernel<<<(N_NODES + 255) / 256, 256>>>();
    scatter_kernel<<<(N_PAIRS + 255) / 256, 256>>>(idx_i, idx_j, phi);

    aggregate_kernel<<<(N_NODES + 7) / 8, 256>>>(w_ij, out);
}